// round 9
// baseline (speedup 1.0000x reference)
#include <cuda_runtime.h>
#include <cstdint>

#define BATCH 8
#define SEQ   2048
#define DIM   1024

#define BM 128
#define BN 128
#define BK 32
#define TPB 256
#define LDR 132   // smem row stride (floats): 128 + 4 pad

#define STAGE_FLOATS (BK * LDR)                   // 4224
#define GEMM_SMEM (4 * STAGE_FLOATS * 4)          // 2 stages x (A+B) = 67584 B

typedef unsigned long long ull;

__device__ __forceinline__ void ffma2(ull& d, ull a, ull b) {
    asm("fma.rn.f32x2 %0, %1, %2, %0;" : "+l"(d) : "l"(a), "l"(b));
}
__device__ __forceinline__ ull dup2(float v) {
    ull r; asm("mov.b64 %0, {%1, %2};" : "=l"(r) : "f"(v), "f"(v)); return r;
}
__device__ __forceinline__ void unpk(ull p, float& lo, float& hi) {
    asm("mov.b64 {%0, %1}, %2;" : "=f"(lo), "=f"(hi) : "l"(p));
}

struct Acc {
    ull a[8][4];
};

// As/Bs: [BK][LDR] transposed tiles (row k, col m/n). B duplicated in regs.
__device__ __forceinline__ void compute_chunk(const float* __restrict__ As,
                                              const float* __restrict__ Bs,
                                              int tm, int tn, Acc& acc) {
#pragma unroll
    for (int k = 0; k < BK; k++) {
        const float* ar = As + k * LDR;
        const float* br = Bs + k * LDR;
        ulonglong2 a01 = *(const ulonglong2*)(ar + tm * 4);
        ulonglong2 a23 = *(const ulonglong2*)(ar + 64 + tm * 4);
        float4 b0 = *(const float4*)(br + tn * 4);
        float4 b1 = *(const float4*)(br + 64 + tn * 4);
        ull ap[4] = {a01.x, a01.y, a23.x, a23.y};
        ull bd[8] = {dup2(b0.x), dup2(b0.y), dup2(b0.z), dup2(b0.w),
                     dup2(b1.x), dup2(b1.y), dup2(b1.z), dup2(b1.w)};
#pragma unroll
        for (int v = 0; v < 8; v++)
#pragma unroll
            for (int p = 0; p < 4; p++) ffma2(acc.a[v][p], ap[p], bd[v]);
    }
}

__device__ __forceinline__ void store_tile(float* dst, size_t ld, int tm, int tn,
                                           const Acc& acc) {
#pragma unroll
    for (int u = 0; u < 8; u++) {
        const int p = u >> 1, hi = u & 1;
        const int r = (u < 4) ? (tm * 4 + u) : (64 + tm * 4 + (u - 4));
        float c[8];
#pragma unroll
        for (int v = 0; v < 8; v++) {
            float lo, hh;
            unpk(acc.a[v][p], lo, hh);
            c[v] = hi ? hh : lo;
        }
        *(float4*)&dst[(size_t)r * ld + tn * 4]      = make_float4(c[0], c[1], c[2], c[3]);
        *(float4*)&dst[(size_t)r * ld + 64 + tn * 4] = make_float4(c[4], c[5], c[6], c[7]);
    }
}

// ---------------------------------------------------------------------------
// Kernel 1: scores S = X X^T, lower-triangular tiles (compacted grid).
// ---------------------------------------------------------------------------
__global__ __launch_bounds__(TPB, 2) void gemm_scores(const float* __restrict__ x,
                                                      float* __restrict__ Sg) {
    const int b = blockIdx.y;
    const int t = blockIdx.x;
    int it = (int)((sqrtf(8.f * (float)t + 1.f) - 1.f) * 0.5f);
    while ((it + 1) * (it + 2) / 2 <= t) ++it;
    while (it * (it + 1) / 2 > t) --it;
    const int jt = t - it * (it + 1) / 2;

    extern __shared__ float sm[];
    float* AsB = sm;                       // [2][BK][LDR]
    float* BsB = sm + 2 * STAGE_FLOATS;    // [2][BK][LDR]

    const float* X = x + (size_t)b * SEQ * DIM;
    float* Sb = Sg + (size_t)b * SEQ * SEQ;

    const int tid = threadIdx.x;
    const int tm = tid / 16, tn = tid % 16;
    const int i0 = it * BM, j0 = jt * BN;
    // 128x32 tile, 1024 float4, 256 thr -> 4 each
    const int lr = tid / 8, lc = (tid % 8) * 4;

    Acc acc;
#pragma unroll
    for (int v = 0; v < 8; v++)
#pragma unroll
        for (int p = 0; p < 4; p++) acc.a[v][p] = 0ull;

    float4 av[4], bv[4];
    auto ldg = [&](int k0) {
#pragma unroll
        for (int q = 0; q < 4; q++) {
            av[q] = *(const float4*)&X[(size_t)(i0 + lr + q * 32) * DIM + k0 + lc];
            bv[q] = *(const float4*)&X[(size_t)(j0 + lr + q * 32) * DIM + k0 + lc];
        }
    };
    auto sts = [&](int s) {
        float* As = AsB + s * STAGE_FLOATS;
        float* Bs = BsB + s * STAGE_FLOATS;
#pragma unroll
        for (int q = 0; q < 4; q++) {
            const int row = lr + q * 32;
            As[(lc + 0) * LDR + row] = av[q].x; As[(lc + 1) * LDR + row] = av[q].y;
            As[(lc + 2) * LDR + row] = av[q].z; As[(lc + 3) * LDR + row] = av[q].w;
            Bs[(lc + 0) * LDR + row] = bv[q].x; Bs[(lc + 1) * LDR + row] = bv[q].y;
            Bs[(lc + 2) * LDR + row] = bv[q].z; Bs[(lc + 3) * LDR + row] = bv[q].w;
        }
    };

    const int NC = DIM / BK;   // 32
    ldg(0);
    sts(0);
    __syncthreads();
    for (int c = 0; c < NC; c++) {
        if (c + 1 < NC) ldg((c + 1) * BK);
        compute_chunk(AsB + (c & 1) * STAGE_FLOATS, BsB + (c & 1) * STAGE_FLOATS, tm, tn, acc);
        if (c + 1 < NC) sts((c + 1) & 1);
        __syncthreads();
    }
    store_tile(&Sb[(size_t)i0 * SEQ + j0], SEQ, tm, tn, acc);
}

// ---------------------------------------------------------------------------
// Kernel 2: softmax rows (strict-lower causal; row0 uniform 1/T), float4.
// ---------------------------------------------------------------------------
__global__ __launch_bounds__(256) void softmax_rows(float* __restrict__ Wg) {
    const int i = blockIdx.x, b = blockIdx.y;
    float* row = Wg + ((size_t)b * SEQ + i) * SEQ;
    const int tid = threadIdx.x;
    if (i == 0) {
        const float v = 1.0f / (float)SEQ;
        const float4 v4 = make_float4(v, v, v, v);
#pragma unroll
        for (int s = 0; s < 2; s++) *(float4*)&row[(tid + s * 256) * 4] = v4;
        return;
    }
    float vals[8];
    float m = -3.0e38f;
#pragma unroll
    for (int s = 0; s < 2; s++) {
        const int j4 = (tid + s * 256) * 4;
        if (j4 < i) {
            float4 v = *(const float4*)&row[j4];
            vals[s * 4 + 0] = (j4 + 0 < i) ? v.x : -3.0e38f;
            vals[s * 4 + 1] = (j4 + 1 < i) ? v.y : -3.0e38f;
            vals[s * 4 + 2] = (j4 + 2 < i) ? v.z : -3.0e38f;
            vals[s * 4 + 3] = (j4 + 3 < i) ? v.w : -3.0e38f;
        } else {
            vals[s * 4 + 0] = vals[s * 4 + 1] = vals[s * 4 + 2] = vals[s * 4 + 3] = -3.0e38f;
        }
#pragma unroll
        for (int e = 0; e < 4; e++) m = fmaxf(m, vals[s * 4 + e]);
    }
    __shared__ float sred[8];
#pragma unroll
    for (int o = 16; o; o >>= 1) m = fmaxf(m, __shfl_xor_sync(0xffffffffu, m, o));
    if ((tid & 31) == 0) sred[tid >> 5] = m;
    __syncthreads();
    m = sred[0];
#pragma unroll
    for (int w = 1; w < 8; w++) m = fmaxf(m, sred[w]);
    float l = 0.f;
#pragma unroll
    for (int s = 0; s < 8; s++) {
        float e = (vals[s] > -1.0e38f) ? __expf(vals[s] - m) : 0.f;
        vals[s] = e;
        l += e;
    }
#pragma unroll
    for (int o = 16; o; o >>= 1) l += __shfl_xor_sync(0xffffffffu, l, o);
    __syncthreads();
    if ((tid & 31) == 0) sred[tid >> 5] = l;
    __syncthreads();
    l = 0.f;
#pragma unroll
    for (int w = 0; w < 8; w++) l += sred[w];
    const float inv = 1.0f / l;
#pragma unroll
    for (int s = 0; s < 2; s++) {
        const int j4 = (tid + s * 256) * 4;
        *(float4*)&row[j4] = make_float4(vals[s * 4 + 0] * inv, vals[s * 4 + 1] * inv,
                                         vals[s * 4 + 2] * inv, vals[s * 4 + 3] * inv);
    }
}

// ---------------------------------------------------------------------------
// Kernel 3: O = W @ X, K bounded at (it+1)*BM; heavy tiles scheduled first.
// ---------------------------------------------------------------------------
__global__ __launch_bounds__(TPB, 2) void gemm_av(const float* __restrict__ Wg,
                                                  const float* __restrict__ x,
                                                  float* __restrict__ Og) {
    const int b = blockIdx.z, dt = blockIdx.x;
    const int it = (SEQ / BM - 1) - blockIdx.y;   // heavy-first

    extern __shared__ float sm[];
    float* AsB = sm;
    float* BsB = sm + 2 * STAGE_FLOATS;

    const float* W = Wg + (size_t)b * SEQ * SEQ;
    const float* X = x + (size_t)b * SEQ * DIM;
    float* Ob = Og + (size_t)b * SEQ * DIM;

    const int tid = threadIdx.x;
    const int tm = tid / 16, tn = tid % 16;
    const int i0 = it * BM, d0 = dt * BN;

    // A (W tile): 128 rows x 32 k, transposed into smem
    const int lrA = tid / 8, lcA = (tid % 8) * 4;
    // B (X tile): 32 k-rows x 128 d, stored direct
    const int krB = tid / 32, dcB = (tid % 32) * 4;

    Acc acc;
#pragma unroll
    for (int v = 0; v < 8; v++)
#pragma unroll
        for (int p = 0; p < 4; p++) acc.a[v][p] = 0ull;

    float4 av[4], bv[4];
    auto ldg = [&](int k0) {
#pragma unroll
        for (int q = 0; q < 4; q++) {
            av[q] = *(const float4*)&W[(size_t)(i0 + lrA + q * 32) * SEQ + k0 + lcA];
            bv[q] = *(const float4*)&X[(size_t)(k0 + krB + q * 8) * DIM + d0 + dcB];
        }
    };
    auto sts = [&](int s) {
        float* As = AsB + s * STAGE_FLOATS;
        float* Bs = BsB + s * STAGE_FLOATS;
#pragma unroll
        for (int q = 0; q < 4; q++) {
            const int row = lrA + q * 32;
            As[(lcA + 0) * LDR + row] = av[q].x; As[(lcA + 1) * LDR + row] = av[q].y;
            As[(lcA + 2) * LDR + row] = av[q].z; As[(lcA + 3) * LDR + row] = av[q].w;
            *(float4*)&Bs[(krB + q * 8) * LDR + dcB] = bv[q];
        }
    };

    const int NC = (it + 1) * (BM / BK);   // causal K bound (4 per row-tile)
    ldg(0);
    sts(0);
    __syncthreads();
    for (int c = 0; c < NC; c++) {
        if (c + 1 < NC) ldg((c + 1) * BK);
        compute_chunk(AsB + (c & 1) * STAGE_FLOATS, BsB + (c & 1) * STAGE_FLOATS, tm, tn, acc);
        if (c + 1 < NC) sts((c + 1) & 1);
        __syncthreads();
    }
    store_tile(&Ob[(size_t)i0 * DIM + d0], DIM, tm, tn, acc);
}

// ---------------------------------------------------------------------------
// Row 0: att_vec[b,0,:] = mean_j x[b,j,:]  (two-stage, 64 slices/batch)
// ---------------------------------------------------------------------------
__device__ float g_r0part[BATCH][64][DIM];

__global__ __launch_bounds__(256) void r0_partial(const float* __restrict__ x) {
    const int b = blockIdx.y, sl = blockIdx.x;
    const float* X = x + (size_t)b * SEQ * DIM;
    const int tid = threadIdx.x;
    float s[4] = {0.f, 0.f, 0.f, 0.f};
    const int j0 = sl * 32;
    for (int j = j0; j < j0 + 32; j++) {
#pragma unroll
        for (int q = 0; q < 4; q++) s[q] += X[(size_t)j * DIM + tid + q * 256];
    }
#pragma unroll
    for (int q = 0; q < 4; q++) g_r0part[b][sl][tid + q * 256] = s[q];
}

__global__ __launch_bounds__(256) void r0_reduce(float* __restrict__ Og) {
    const int b = blockIdx.y;
    const int d = blockIdx.x * 256 + threadIdx.x;
    float s = 0.f;
#pragma unroll
    for (int sl = 0; sl < 64; sl++) s += g_r0part[b][sl][d];
    Og[(size_t)b * SEQ * DIM + d] = s * (1.0f / (float)SEQ);
}

// ---------------------------------------------------------------------------
extern "C" void kernel_launch(void* const* d_in, const int* in_sizes, int n_in,
                              void* d_out, int out_size) {
    const float* x = (const float*)d_in[0];
    float* out     = (float*)d_out;
    float* att_vec = out;                                   // [B,T,D]
    float* Wg      = out + (size_t)BATCH * SEQ * DIM;       // [B,T,T]

    static int configured = 0;
    if (!configured) {
        cudaFuncSetAttribute(gemm_scores, cudaFuncAttributeMaxDynamicSharedMemorySize, GEMM_SMEM);
        cudaFuncSetAttribute(gemm_av, cudaFuncAttributeMaxDynamicSharedMemorySize, GEMM_SMEM);
        configured = 1;
    }

    const int NT = SEQ / BM;                  // 16
    dim3 g1(NT * (NT + 1) / 2, BATCH);        // 136 lower-tri tiles/batch
    gemm_scores<<<g1, TPB, GEMM_SMEM>>>(x, Wg);

    dim3 g2(SEQ, BATCH);
    softmax_rows<<<g2, 256>>>(Wg);

    dim3 g3(DIM / BN, SEQ / BM, BATCH);
    gemm_av<<<g3, TPB, GEMM_SMEM>>>(Wg, x, att_vec);

    dim3 g4(64, BATCH);
    r0_partial<<<g4, 256>>>(x);
    dim3 g5(DIM / 256, BATCH);
    r0_reduce<<<g5, 256>>>(att_vec);
}

// round 11
// speedup vs baseline: 1.0367x; 1.0367x over previous
#include <cuda_runtime.h>
#include <cstdint>

#define BATCH 8
#define SEQ   2048
#define DIM   1024

#define BM 128
#define BN 128
#define BK 16
#define TPB 256

typedef unsigned long long ull;

// 64MB transposed X scratch: g_xt[b][d][t]
__device__ float g_xt[(size_t)BATCH * DIM * SEQ];
__device__ float g_r0part[BATCH][64][DIM];

__device__ __forceinline__ void ffma2(ull& d, ull a, ull b) {
    asm("fma.rn.f32x2 %0, %1, %2, %0;" : "+l"(d) : "l"(a), "l"(b));
}
__device__ __forceinline__ ull dup2(float v) {
    ull r; asm("mov.b64 %0, {%1, %2};" : "=l"(r) : "f"(v), "f"(v)); return r;
}
__device__ __forceinline__ void unpk(ull p, float& lo, float& hi) {
    asm("mov.b64 {%0, %1}, %2;" : "=f"(lo), "=f"(hi) : "l"(p));
}
__device__ __forceinline__ uint32_t s2u(const void* p) {
    uint32_t a;
    asm("{ .reg .u64 t; cvta.to.shared.u64 t, %1; cvt.u32.u64 %0, t; }" : "=r"(a) : "l"(p));
    return a;
}
__device__ __forceinline__ void cpa16(uint32_t dst, const void* src) {
    asm volatile("cp.async.cg.shared.global [%0], [%1], 16;" :: "r"(dst), "l"(src));
}
#define CP_COMMIT() asm volatile("cp.async.commit_group;" ::: "memory")
#define CP_WAIT1()  asm volatile("cp.async.wait_group 1;" ::: "memory")
#define CP_WAIT0()  asm volatile("cp.async.wait_group 0;" ::: "memory")

// ---------------------------------------------------------------------------
// Transpose: g_xt[b][d][t] = x[b][t][d]
// ---------------------------------------------------------------------------
__global__ __launch_bounds__(256) void transpose_x(const float* __restrict__ x) {
    __shared__ float tile[32][33];
    const int b = blockIdx.z;
    const int t0 = blockIdx.x * 32, d0 = blockIdx.y * 32;
    const int tx = threadIdx.x & 31, ty = threadIdx.x >> 5;  // 32x8
    const float* X = x + (size_t)b * SEQ * DIM;
    float* Xt = g_xt + (size_t)b * DIM * SEQ;
#pragma unroll
    for (int j = 0; j < 32; j += 8)
        tile[ty + j][tx] = X[(size_t)(t0 + ty + j) * DIM + d0 + tx];
    __syncthreads();
#pragma unroll
    for (int j = 0; j < 32; j += 8)
        Xt[(size_t)(d0 + ty + j) * SEQ + t0 + tx] = tile[tx][ty + j];
}

// ---------------------------------------------------------------------------
// Kernel 1: scores S = X X^T, lower-tri tiles. Operands from g_xt ([k][m]).
// 3-stage cp.async pipeline. m-packed FFMA2 (pairs along m).
// ---------------------------------------------------------------------------
#define S_STAGE 4096                        // floats per stage (A 2048 | B 2048)
#define S_SMEM  (3 * S_STAGE * 4)           // 49152 B

struct AccM { ull a[8][4]; };               // [n-col][m-pair]

__global__ __launch_bounds__(TPB, 2) void gemm_scores(float* __restrict__ Sg) {
    const int b = blockIdx.y;
    const int t = blockIdx.x;
    int it = (int)((sqrtf(8.f * (float)t + 1.f) - 1.f) * 0.5f);
    while ((it + 1) * (it + 2) / 2 <= t) ++it;
    while (it * (it + 1) / 2 > t) --it;
    const int jt = t - it * (it + 1) / 2;

    extern __shared__ float sm[];
    const float* Xt = g_xt + (size_t)b * DIM * SEQ;
    float* Sb = Sg + (size_t)b * SEQ * SEQ;

    const int tid = threadIdx.x;
    const int tm = tid / 16, tn = tid % 16;
    const int i0 = it * BM, j0 = jt * BN;
    const int lk = tid >> 5, lm4 = (tid & 31) << 2;

    AccM acc;
#pragma unroll
    for (int v = 0; v < 8; v++)
#pragma unroll
        for (int p = 0; p < 4; p++) acc.a[v][p] = 0ull;

    auto ldg = [&](int s, int c) {
        const int kk = c * BK;
        float* As = sm + s * S_STAGE;
        float* Bs = As + 2048;
#pragma unroll
        for (int itr = 0; itr < 2; itr++) {
            const int k = lk + itr * 8;
            cpa16(s2u(&As[k * 128 + lm4]), &Xt[(size_t)(kk + k) * SEQ + i0 + lm4]);
            cpa16(s2u(&Bs[k * 128 + lm4]), &Xt[(size_t)(kk + k) * SEQ + j0 + lm4]);
        }
        CP_COMMIT();
    };
    auto compute = [&](int s) {
        const float* As = sm + s * S_STAGE;
        const float* Bs = As + 2048;
#pragma unroll
        for (int k = 0; k < BK; k++) {
            ulonglong2 a01 = *(const ulonglong2*)&As[k * 128 + tm * 4];
            ulonglong2 a23 = *(const ulonglong2*)&As[k * 128 + 64 + tm * 4];
            float4 b0 = *(const float4*)&Bs[k * 128 + tn * 4];
            float4 b1 = *(const float4*)&Bs[k * 128 + 64 + tn * 4];
            ull ap[4] = {a01.x, a01.y, a23.x, a23.y};
            ull bd[8] = {dup2(b0.x), dup2(b0.y), dup2(b0.z), dup2(b0.w),
                         dup2(b1.x), dup2(b1.y), dup2(b1.z), dup2(b1.w)};
#pragma unroll
            for (int v = 0; v < 8; v++)
#pragma unroll
                for (int p = 0; p < 4; p++) ffma2(acc.a[v][p], ap[p], bd[v]);
        }
    };

    const int NC = DIM / BK;   // 64
    ldg(0, 0);
    ldg(1, 1);
    for (int c = 0; c < NC; c++) {
        if (c + 1 < NC) { CP_WAIT1(); } else { CP_WAIT0(); }
        __syncthreads();
        if (c + 2 < NC) ldg((c + 2) % 3, c + 2);
        compute(c % 3);
    }

#pragma unroll
    for (int u = 0; u < 8; u++) {
        const int p = u >> 1, hi = u & 1;
        const int r = (u < 4) ? (tm * 4 + u) : (64 + tm * 4 + (u - 4));
        float cvals[8];
#pragma unroll
        for (int v = 0; v < 8; v++) {
            float lo, hh;
            unpk(acc.a[v][p], lo, hh);
            cvals[v] = hi ? hh : lo;
        }
        *(float4*)&Sb[(size_t)(i0 + r) * SEQ + j0 + tn * 4] =
            make_float4(cvals[0], cvals[1], cvals[2], cvals[3]);
        *(float4*)&Sb[(size_t)(i0 + r) * SEQ + j0 + 64 + tn * 4] =
            make_float4(cvals[4], cvals[5], cvals[6], cvals[7]);
    }
}

// ---------------------------------------------------------------------------
// Kernel 2: softmax rows (strict-lower causal; row0 uniform 1/T), float4.
// ---------------------------------------------------------------------------
__global__ __launch_bounds__(256) void softmax_rows(float* __restrict__ Wg) {
    const int i = blockIdx.x, b = blockIdx.y;
    float* row = Wg + ((size_t)b * SEQ + i) * SEQ;
    const int tid = threadIdx.x;
    if (i == 0) {
        const float v = 1.0f / (float)SEQ;
        const float4 v4 = make_float4(v, v, v, v);
#pragma unroll
        for (int s = 0; s < 2; s++) *(float4*)&row[(tid + s * 256) * 4] = v4;
        return;
    }
    float vals[8];
    float m = -3.0e38f;
#pragma unroll
    for (int s = 0; s < 2; s++) {
        const int j4 = (tid + s * 256) * 4;
        if (j4 < i) {
            float4 v = *(const float4*)&row[j4];
            vals[s * 4 + 0] = (j4 + 0 < i) ? v.x : -3.0e38f;
            vals[s * 4 + 1] = (j4 + 1 < i) ? v.y : -3.0e38f;
            vals[s * 4 + 2] = (j4 + 2 < i) ? v.z : -3.0e38f;
            vals[s * 4 + 3] = (j4 + 3 < i) ? v.w : -3.0e38f;
        } else {
            vals[s * 4 + 0] = vals[s * 4 + 1] = vals[s * 4 + 2] = vals[s * 4 + 3] = -3.0e38f;
        }
#pragma unroll
        for (int e = 0; e < 4; e++) m = fmaxf(m, vals[s * 4 + e]);
    }
    __shared__ float sred[8];
#pragma unroll
    for (int o = 16; o; o >>= 1) m = fmaxf(m, __shfl_xor_sync(0xffffffffu, m, o));
    if ((tid & 31) == 0) sred[tid >> 5] = m;
    __syncthreads();
    m = sred[0];
#pragma unroll
    for (int w = 1; w < 8; w++) m = fmaxf(m, sred[w]);
    float l = 0.f;
#pragma unroll
    for (int s = 0; s < 8; s++) {
        float e = (vals[s] > -1.0e38f) ? __expf(vals[s] - m) : 0.f;
        vals[s] = e;
        l += e;
    }
#pragma unroll
    for (int o = 16; o; o >>= 1) l += __shfl_xor_sync(0xffffffffu, l, o);
    __syncthreads();
    if ((tid & 31) == 0) sred[tid >> 5] = l;
    __syncthreads();
    l = 0.f;
#pragma unroll
    for (int w = 0; w < 8; w++) l += sred[w];
    const float inv = 1.0f / l;
#pragma unroll
    for (int s = 0; s < 2; s++) {
        const int j4 = (tid + s * 256) * 4;
        *(float4*)&row[j4] = make_float4(vals[s * 4 + 0] * inv, vals[s * 4 + 1] * inv,
                                         vals[s * 4 + 2] * inv, vals[s * 4 + 3] * inv);
    }
}

// ---------------------------------------------------------------------------
// Kernel 3: O = W @ X. n-packed FFMA2; A (W) natural [m][k] (LDK=20 pad),
// B (X) natural [k][d]; both staged via cp.async. K bounded at (it+1)*BM.
// ---------------------------------------------------------------------------
#define A_LDK   20
#define V_STAGE (128 * A_LDK + 2048)        // 4608 floats (A 2560 | B 2048)
#define V_SMEM  (3 * V_STAGE * 4)           // 55296 B

__global__ __launch_bounds__(TPB, 2) void gemm_av(const float* __restrict__ Wg,
                                                  const float* __restrict__ x,
                                                  float* __restrict__ Og) {
    const int b = blockIdx.z, dt = blockIdx.x;
    const int it = (SEQ / BM - 1) - blockIdx.y;   // heavy-first

    extern __shared__ float sm[];
    const float* W = Wg + (size_t)b * SEQ * SEQ;
    const float* X = x + (size_t)b * SEQ * DIM;
    float* Ob = Og + (size_t)b * SEQ * DIM;

    const int tid = threadIdx.x;
    const int tm = tid / 16, tn = tid % 16;
    const int i0 = it * BM, d0 = dt * BN;

    AccM acc;   // [m-row u][n-pair p]
#pragma unroll
    for (int u = 0; u < 8; u++)
#pragma unroll
        for (int p = 0; p < 4; p++) acc.a[u][p] = 0ull;

    auto ldg = [&](int s, int c) {
        const int kk = c * BK;
        float* As = sm + s * V_STAGE;
        float* Bs = As + 128 * A_LDK;
#pragma unroll
        for (int itr = 0; itr < 2; itr++) {
            const int e = tid + itr * 256;
            const int m = e >> 2, ko = (e & 3) << 2;
            cpa16(s2u(&As[m * A_LDK + ko]), &W[(size_t)(i0 + m) * SEQ + kk + ko]);
            const int k = e >> 5, d4 = (e & 31) << 2;
            cpa16(s2u(&Bs[k * 128 + d4]), &X[(size_t)(kk + k) * DIM + d0 + d4]);
        }
        CP_COMMIT();
    };
    auto compute = [&](int s) {
        const float* As = sm + s * V_STAGE;
        const float* Bs = As + 128 * A_LDK;
#pragma unroll
        for (int k = 0; k < BK; k++) {
            float a8[8];
#pragma unroll
            for (int u = 0; u < 4; u++) {
                a8[u]     = As[(tm * 4 + u) * A_LDK + k];
                a8[u + 4] = As[(64 + tm * 4 + u) * A_LDK + k];
            }
            ulonglong2 q0 = *(const ulonglong2*)&Bs[k * 128 + tn * 4];
            ulonglong2 q1 = *(const ulonglong2*)&Bs[k * 128 + 64 + tn * 4];
            ull bp[4] = {q0.x, q0.y, q1.x, q1.y};
            ull ad[8];
#pragma unroll
            for (int u = 0; u < 8; u++) ad[u] = dup2(a8[u]);
#pragma unroll
            for (int u = 0; u < 8; u++)
#pragma unroll
                for (int p = 0; p < 4; p++) ffma2(acc.a[u][p], ad[u], bp[p]);
        }
    };

    const int NC = (it + 1) * (BM / BK);   // causal K bound
    ldg(0, 0);
    ldg(1, 1);
    for (int c = 0; c < NC; c++) {
        if (c + 1 < NC) { CP_WAIT1(); } else { CP_WAIT0(); }
        __syncthreads();
        if (c + 2 < NC) ldg((c + 2) % 3, c + 2);
        compute(c % 3);
    }

#pragma unroll
    for (int u = 0; u < 8; u++) {
        const int r = (u < 4) ? (tm * 4 + u) : (64 + tm * 4 + (u - 4));
        float c0, c1, c2, c3, c4, c5, c6, c7;
        unpk(acc.a[u][0], c0, c1);
        unpk(acc.a[u][1], c2, c3);
        unpk(acc.a[u][2], c4, c5);
        unpk(acc.a[u][3], c6, c7);
        *(float4*)&Ob[(size_t)(i0 + r) * DIM + d0 + tn * 4]      = make_float4(c0, c1, c2, c3);
        *(float4*)&Ob[(size_t)(i0 + r) * DIM + d0 + 64 + tn * 4] = make_float4(c4, c5, c6, c7);
    }
}

// ---------------------------------------------------------------------------
// Row 0: att_vec[b,0,:] = mean_j x[b,j,:]  (two-stage, 64 slices/batch)
// ---------------------------------------------------------------------------
__global__ __launch_bounds__(256) void r0_partial(const float* __restrict__ x) {
    const int b = blockIdx.y, sl = blockIdx.x;
    const float* X = x + (size_t)b * SEQ * DIM;
    const int tid = threadIdx.x;
    float s[4] = {0.f, 0.f, 0.f, 0.f};
    const int j0 = sl * 32;
    for (int j = j0; j < j0 + 32; j++) {
#pragma unroll
        for (int q = 0; q < 4; q++) s[q] += X[(size_t)j * DIM + tid + q * 256];
    }
#pragma unroll
    for (int q = 0; q < 4; q++) g_r0part[b][sl][tid + q * 256] = s[q];
}

__global__ __launch_bounds__(256) void r0_reduce(float* __restrict__ Og) {
    const int b = blockIdx.y;
    const int d = blockIdx.x * 256 + threadIdx.x;
    float s = 0.f;
#pragma unroll
    for (int sl = 0; sl < 64; sl++) s += g_r0part[b][sl][d];
    Og[(size_t)b * SEQ * DIM + d] = s * (1.0f / (float)SEQ);
}

// ---------------------------------------------------------------------------
extern "C" void kernel_launch(void* const* d_in, const int* in_sizes, int n_in,
                              void* d_out, int out_size) {
    const float* x = (const float*)d_in[0];
    float* out     = (float*)d_out;
    float* att_vec = out;                                   // [B,T,D]
    float* Wg      = out + (size_t)BATCH * SEQ * DIM;       // [B,T,T]

    cudaFuncSetAttribute(gemm_scores, cudaFuncAttributeMaxDynamicSharedMemorySize, S_SMEM);
    cudaFuncSetAttribute(gemm_av, cudaFuncAttributeMaxDynamicSharedMemorySize, V_SMEM);

    dim3 gt(SEQ / 32, DIM / 32, BATCH);
    transpose_x<<<gt, 256>>>(x);

    const int NT = SEQ / BM;                  // 16
    dim3 g1(NT * (NT + 1) / 2, BATCH);        // 136 lower-tri tiles/batch
    gemm_scores<<<g1, TPB, S_SMEM>>>(Wg);

    dim3 g2(SEQ, BATCH);
    softmax_rows<<<g2, 256>>>(Wg);

    dim3 g3(DIM / BN, SEQ / BM, BATCH);
    gemm_av<<<g3, TPB, V_SMEM>>>(Wg, x, att_vec);

    dim3 g4(64, BATCH);
    r0_partial<<<g4, 256>>>(x);
    dim3 g5(DIM / 256, BATCH);
    r0_reduce<<<g5, 256>>>(att_vec);
}

// round 13
// speedup vs baseline: 1.1407x; 1.1003x over previous
#include <cuda_runtime.h>
#include <cstdint>

#define BATCH 8
#define SEQ   2048
#define DIM   1024

#define BM 128
#define BN 128
#define BK 16
#define TPB 256
#define LDR 132   // padded [k][m] row stride for transposed-A staging (floats)

typedef unsigned long long ull;

// 64MB transposed X scratch: g_xt[b][d][t]
__device__ float g_xt[(size_t)BATCH * DIM * SEQ];
__device__ float g_r0part[BATCH][64][DIM];

__device__ __forceinline__ void ffma2(ull& d, ull a, ull b) {
    asm("fma.rn.f32x2 %0, %1, %2, %0;" : "+l"(d) : "l"(a), "l"(b));
}
__device__ __forceinline__ ull dup2(float v) {
    ull r; asm("mov.b64 %0, {%1, %2};" : "=l"(r) : "f"(v), "f"(v)); return r;
}
__device__ __forceinline__ void unpk(ull p, float& lo, float& hi) {
    asm("mov.b64 {%0, %1}, %2;" : "=f"(lo), "=f"(hi) : "l"(p));
}
__device__ __forceinline__ uint32_t s2u(const void* p) {
    uint32_t a;
    asm("{ .reg .u64 t; cvta.to.shared.u64 t, %1; cvt.u32.u64 %0, t; }" : "=r"(a) : "l"(p));
    return a;
}
__device__ __forceinline__ void cpa16(uint32_t dst, const void* src) {
    asm volatile("cp.async.cg.shared.global [%0], [%1], 16;" :: "r"(dst), "l"(src));
}
#define CP_COMMIT() asm volatile("cp.async.commit_group;" ::: "memory")
#define CP_WAIT1()  asm volatile("cp.async.wait_group 1;" ::: "memory")
#define CP_WAIT0()  asm volatile("cp.async.wait_group 0;" ::: "memory")

struct AccM { ull a[8][4]; };   // [n-col][m-pair]

// m-packed inner product: As [k][m] (stride LDA_), Bs [k][n] (stride LDB_).
// Per k: 4x LDS.128 + 8 mov.b64 + 32 FFMA2.
template <int LDA_, int LDB_>
__device__ __forceinline__ void compute_mp(const float* __restrict__ As,
                                           const float* __restrict__ Bs,
                                           int tm, int tn, AccM& acc) {
#pragma unroll
    for (int k = 0; k < BK; k++) {
        ulonglong2 a01 = *(const ulonglong2*)&As[k * LDA_ + tm * 4];
        ulonglong2 a23 = *(const ulonglong2*)&As[k * LDA_ + 64 + tm * 4];
        float4 b0 = *(const float4*)&Bs[k * LDB_ + tn * 4];
        float4 b1 = *(const float4*)&Bs[k * LDB_ + 64 + tn * 4];
        ull ap[4] = {a01.x, a01.y, a23.x, a23.y};
        ull bd[8] = {dup2(b0.x), dup2(b0.y), dup2(b0.z), dup2(b0.w),
                     dup2(b1.x), dup2(b1.y), dup2(b1.z), dup2(b1.w)};
#pragma unroll
        for (int v = 0; v < 8; v++)
#pragma unroll
            for (int p = 0; p < 4; p++) ffma2(acc.a[v][p], ap[p], bd[v]);
    }
}

__device__ __forceinline__ void store_tile(float* dst, size_t ld, int tm, int tn,
                                           const AccM& acc) {
#pragma unroll
    for (int u = 0; u < 8; u++) {
        const int p = u >> 1, hi = u & 1;
        const int r = (u < 4) ? (tm * 4 + u) : (64 + tm * 4 + (u - 4));
        float c[8];
#pragma unroll
        for (int v = 0; v < 8; v++) {
            float lo, hh;
            unpk(acc.a[v][p], lo, hh);
            c[v] = hi ? hh : lo;
        }
        *(float4*)&dst[(size_t)r * ld + tn * 4]      = make_float4(c[0], c[1], c[2], c[3]);
        *(float4*)&dst[(size_t)r * ld + 64 + tn * 4] = make_float4(c[4], c[5], c[6], c[7]);
    }
}

// ---------------------------------------------------------------------------
// Transpose: g_xt[b][d][t] = x[b][t][d]
// ---------------------------------------------------------------------------
__global__ __launch_bounds__(256) void transpose_x(const float* __restrict__ x) {
    __shared__ float tile[32][33];
    const int b = blockIdx.z;
    const int t0 = blockIdx.x * 32, d0 = blockIdx.y * 32;
    const int tx = threadIdx.x & 31, ty = threadIdx.x >> 5;  // 32x8
    const float* X = x + (size_t)b * SEQ * DIM;
    float* Xt = g_xt + (size_t)b * DIM * SEQ;
#pragma unroll
    for (int j = 0; j < 32; j += 8)
        tile[ty + j][tx] = X[(size_t)(t0 + ty + j) * DIM + d0 + tx];
    __syncthreads();
#pragma unroll
    for (int j = 0; j < 32; j += 8)
        Xt[(size_t)(d0 + ty + j) * SEQ + t0 + tx] = tile[tx][ty + j];
}

// ---------------------------------------------------------------------------
// Kernel 1: scores S = X X^T, lower-tri tiles; both operands from g_xt [k][m].
// 3-stage cp.async pipeline. Stage stride = 128 (contiguous).
// ---------------------------------------------------------------------------
#define S_STAGE 4096                        // floats per stage (A 2048 | B 2048)
#define S_SMEM  (3 * S_STAGE * 4)           // 49152 B

__global__ __launch_bounds__(TPB, 2) void gemm_scores(float* __restrict__ Sg) {
    const int b = blockIdx.y;
    const int t = blockIdx.x;
    int it = (int)((sqrtf(8.f * (float)t + 1.f) - 1.f) * 0.5f);
    while ((it + 1) * (it + 2) / 2 <= t) ++it;
    while (it * (it + 1) / 2 > t) --it;
    const int jt = t - it * (it + 1) / 2;

    extern __shared__ float sm[];
    const float* Xt = g_xt + (size_t)b * DIM * SEQ;
    float* Sb = Sg + (size_t)b * SEQ * SEQ;

    const int tid = threadIdx.x;
    const int tm = tid / 16, tn = tid % 16;
    const int i0 = it * BM, j0 = jt * BN;
    const int lk = tid >> 5, lm4 = (tid & 31) << 2;

    AccM acc;
#pragma unroll
    for (int v = 0; v < 8; v++)
#pragma unroll
        for (int p = 0; p < 4; p++) acc.a[v][p] = 0ull;

    auto ldg = [&](int s, int c) {
        const int kk = c * BK;
        float* As = sm + s * S_STAGE;
        float* Bs = As + 2048;
#pragma unroll
        for (int itr = 0; itr < 2; itr++) {
            const int k = lk + itr * 8;
            cpa16(s2u(&As[k * 128 + lm4]), &Xt[(size_t)(kk + k) * SEQ + i0 + lm4]);
            cpa16(s2u(&Bs[k * 128 + lm4]), &Xt[(size_t)(kk + k) * SEQ + j0 + lm4]);
        }
        CP_COMMIT();
    };

    const int NC = DIM / BK;   // 64
    ldg(0, 0);
    ldg(1, 1);
    for (int c = 0; c < NC; c++) {
        if (c + 1 < NC) { CP_WAIT1(); } else { CP_WAIT0(); }
        __syncthreads();
        if (c + 2 < NC) ldg((c + 2) % 3, c + 2);
        compute_mp<128, 128>(sm + (c % 3) * S_STAGE, sm + (c % 3) * S_STAGE + 2048, tm, tn, acc);
    }
    store_tile(&Sb[(size_t)i0 * SEQ + j0], SEQ, tm, tn, acc);
}

// ---------------------------------------------------------------------------
// Kernel 2: softmax rows (strict-lower causal; row0 uniform 1/T), float4.
// ---------------------------------------------------------------------------
__global__ __launch_bounds__(256) void softmax_rows(float* __restrict__ Wg) {
    const int i = blockIdx.x, b = blockIdx.y;
    float* row = Wg + ((size_t)b * SEQ + i) * SEQ;
    const int tid = threadIdx.x;
    if (i == 0) {
        const float v = 1.0f / (float)SEQ;
        const float4 v4 = make_float4(v, v, v, v);
#pragma unroll
        for (int s = 0; s < 2; s++) *(float4*)&row[(tid + s * 256) * 4] = v4;
        return;
    }
    float vals[8];
    float m = -3.0e38f;
#pragma unroll
    for (int s = 0; s < 2; s++) {
        const int j4 = (tid + s * 256) * 4;
        if (j4 < i) {
            float4 v = *(const float4*)&row[j4];
            vals[s * 4 + 0] = (j4 + 0 < i) ? v.x : -3.0e38f;
            vals[s * 4 + 1] = (j4 + 1 < i) ? v.y : -3.0e38f;
            vals[s * 4 + 2] = (j4 + 2 < i) ? v.z : -3.0e38f;
            vals[s * 4 + 3] = (j4 + 3 < i) ? v.w : -3.0e38f;
        } else {
            vals[s * 4 + 0] = vals[s * 4 + 1] = vals[s * 4 + 2] = vals[s * 4 + 3] = -3.0e38f;
        }
#pragma unroll
        for (int e = 0; e < 4; e++) m = fmaxf(m, vals[s * 4 + e]);
    }
    __shared__ float sred[8];
#pragma unroll
    for (int o = 16; o; o >>= 1) m = fmaxf(m, __shfl_xor_sync(0xffffffffu, m, o));
    if ((tid & 31) == 0) sred[tid >> 5] = m;
    __syncthreads();
    m = sred[0];
#pragma unroll
    for (int w = 1; w < 8; w++) m = fmaxf(m, sred[w]);
    float l = 0.f;
#pragma unroll
    for (int s = 0; s < 8; s++) {
        float e = (vals[s] > -1.0e38f) ? __expf(vals[s] - m) : 0.f;
        vals[s] = e;
        l += e;
    }
#pragma unroll
    for (int o = 16; o; o >>= 1) l += __shfl_xor_sync(0xffffffffu, l, o);
    __syncthreads();
    if ((tid & 31) == 0) sred[tid >> 5] = l;
    __syncthreads();
    l = 0.f;
#pragma unroll
    for (int w = 0; w < 8; w++) l += sred[w];
    const float inv = 1.0f / l;
#pragma unroll
    for (int s = 0; s < 2; s++) {
        const int j4 = (tid + s * 256) * 4;
        *(float4*)&row[j4] = make_float4(vals[s * 4 + 0] * inv, vals[s * 4 + 1] * inv,
                                         vals[s * 4 + 2] * inv, vals[s * 4 + 3] * inv);
    }
}

// ---------------------------------------------------------------------------
// Kernel 3: O = W @ X, m-packed. A (W) LDG-prefetch + transposed STS ([k][m],
// stride LDR=132); B (X, natural [k][d], stride 128) via cp.async.
// K bounded at (it+1)*BM.
// ---------------------------------------------------------------------------
__global__ __launch_bounds__(TPB, 2) void gemm_av(const float* __restrict__ Wg,
                                                  const float* __restrict__ x,
                                                  float* __restrict__ Og) {
    const int b = blockIdx.z, dt = blockIdx.x;
    const int it = (SEQ / BM - 1) - blockIdx.y;   // heavy-first

    __shared__ float As[2][BK][LDR];
    __shared__ float Bs[2][BK][128];

    const float* W = Wg + (size_t)b * SEQ * SEQ;
    const float* X = x + (size_t)b * SEQ * DIM;
    float* Ob = Og + (size_t)b * SEQ * DIM;

    const int tid = threadIdx.x;
    const int tm = tid / 16, tn = tid % 16;
    const int i0 = it * BM, d0 = dt * BN;
    const int lrA = tid / 4, lcA = (tid % 4) * 4;

    AccM acc;
#pragma unroll
    for (int v = 0; v < 8; v++)
#pragma unroll
        for (int p = 0; p < 4; p++) acc.a[v][p] = 0ull;

    float4 a0, a1;
    auto ldgA = [&](int k0) {
        a0 = *(const float4*)&W[(size_t)(i0 + lrA)      * SEQ + k0 + lcA];
        a1 = *(const float4*)&W[(size_t)(i0 + lrA + 64) * SEQ + k0 + lcA];
    };
    auto stsA = [&](int s) {
        As[s][lcA + 0][lrA] = a0.x; As[s][lcA + 1][lrA] = a0.y;
        As[s][lcA + 2][lrA] = a0.z; As[s][lcA + 3][lrA] = a0.w;
        As[s][lcA + 0][lrA + 64] = a1.x; As[s][lcA + 1][lrA + 64] = a1.y;
        As[s][lcA + 2][lrA + 64] = a1.z; As[s][lcA + 3][lrA + 64] = a1.w;
    };
    auto cpaB = [&](int s, int c) {
        const int k0 = c * BK;
#pragma unroll
        for (int itr = 0; itr < 2; itr++) {
            const int e = tid + itr * 256;
            const int k = e >> 5, d4 = (e & 31) << 2;
            cpa16(s2u(&Bs[s][k][d4]), &X[(size_t)(k0 + k) * DIM + d0 + d4]);
        }
        CP_COMMIT();
    };

    const int NC = (it + 1) * (BM / BK);   // causal K bound
    ldgA(0);
    cpaB(0, 0);
    stsA(0);
    CP_WAIT0();
    __syncthreads();
    for (int c = 0; c < NC; c++) {
        if (c + 1 < NC) { ldgA((c + 1) * BK); cpaB((c + 1) & 1, c + 1); }
        compute_mp<LDR, 128>(&As[c & 1][0][0], &Bs[c & 1][0][0], tm, tn, acc);
        if (c + 1 < NC) { stsA((c + 1) & 1); CP_WAIT0(); }
        __syncthreads();
    }
    store_tile(&Ob[(size_t)i0 * DIM + d0], DIM, tm, tn, acc);
}

// ---------------------------------------------------------------------------
// Row 0: att_vec[b,0,:] = mean_j x[b,j,:]  (two-stage, 64 slices/batch)
// ---------------------------------------------------------------------------
__global__ __launch_bounds__(256) void r0_partial(const float* __restrict__ x) {
    const int b = blockIdx.y, sl = blockIdx.x;
    const float* X = x + (size_t)b * SEQ * DIM;
    const int tid = threadIdx.x;
    float s[4] = {0.f, 0.f, 0.f, 0.f};
    const int j0 = sl * 32;
    for (int j = j0; j < j0 + 32; j++) {
#pragma unroll
        for (int q = 0; q < 4; q++) s[q] += X[(size_t)j * DIM + tid + q * 256];
    }
#pragma unroll
    for (int q = 0; q < 4; q++) g_r0part[b][sl][tid + q * 256] = s[q];
}

__global__ __launch_bounds__(256) void r0_reduce(float* __restrict__ Og) {
    const int b = blockIdx.y;
    const int d = blockIdx.x * 256 + threadIdx.x;
    float s = 0.f;
#pragma unroll
    for (int sl = 0; sl < 64; sl++) s += g_r0part[b][sl][d];
    Og[(size_t)b * SEQ * DIM + d] = s * (1.0f / (float)SEQ);
}

// ---------------------------------------------------------------------------
extern "C" void kernel_launch(void* const* d_in, const int* in_sizes, int n_in,
                              void* d_out, int out_size) {
    const float* x = (const float*)d_in[0];
    float* out     = (float*)d_out;
    float* att_vec = out;                                   // [B,T,D]
    float* Wg      = out + (size_t)BATCH * SEQ * DIM;       // [B,T,T]

    cudaFuncSetAttribute(gemm_scores, cudaFuncAttributeMaxDynamicSharedMemorySize, S_SMEM);

    dim3 gt(SEQ / 32, DIM / 32, BATCH);
    transpose_x<<<gt, 256>>>(x);

    const int NT = SEQ / BM;                  // 16
    dim3 g1(NT * (NT + 1) / 2, BATCH);        // 136 lower-tri tiles/batch
    gemm_scores<<<g1, TPB, S_SMEM>>>(Wg);

    dim3 g2(SEQ, BATCH);
    softmax_rows<<<g2, 256>>>(Wg);

    dim3 g3(DIM / BN, SEQ / BM, BATCH);
    gemm_av<<<g3, TPB>>>(Wg, x, att_vec);

    dim3 g4(64, BATCH);
    r0_partial<<<g4, 256>>>(x);
    dim3 g5(DIM / 256, BATCH);
    r0_reduce<<<g5, 256>>>(att_vec);
}